// round 8
// baseline (speedup 1.0000x reference)
#include <cuda_runtime.h>
#include <cstdint>

// Problem constants
#define T_DIM 1024
#define B_DIM 4
#define S_DIM 1024
#define E_DIM 1024
#define H_DIM 16
#define D_DIM 64
#define TB (T_DIM * B_DIM)
#define BE (B_DIM * E_DIM)

// Scratch (device globals — no allocation allowed)
__device__ float g_Q[TB * E_DIM];
__device__ float g_K[TB * E_DIM];
__device__ float g_V[TB * E_DIM];
__device__ float g_Ctx[TB * E_DIM];
__device__ float g_P[(long)B_DIM * H_DIM * T_DIM * S_DIM];   // scores -> probs (256 MB)

// ---------------------------------------------------------------------------
// tf32 helpers
// ---------------------------------------------------------------------------
__device__ __forceinline__ uint32_t f2tf(float x) {
    uint32_t r;
    asm("cvt.rna.tf32.f32 %0, %1;" : "=r"(r) : "f"(x));
    return r;
}

__device__ __forceinline__ void mma8(float* d, const uint32_t* a, const uint32_t* b) {
    asm volatile(
        "mma.sync.aligned.m16n8k8.row.col.f32.tf32.tf32.f32 "
        "{%0,%1,%2,%3}, {%4,%5,%6,%7}, {%8,%9}, {%0,%1,%2,%3};\n"
        : "+f"(d[0]), "+f"(d[1]), "+f"(d[2]), "+f"(d[3])
        : "r"(a[0]), "r"(a[1]), "r"(a[2]), "r"(a[3]), "r"(b[0]), "r"(b[1]));
}

#define PBK 32
#define LDA 132

#define GEMM_SMEM_BYTES (2 * PBK * LDA * 2 * 4)   // 67584 (double-buffered A+B)

// ---------------------------------------------------------------------------
// 512-thread double-buffered 128x128x32 tf32 GEMM core.
// 16 warps (4m x 4n), warp tile 32x32 -> acc 32 regs/thread.
// ---------------------------------------------------------------------------
#define GEMM_DB_CORE(APTR, WPTR)                                              \
    const int lrow = tid >> 3, lkc = (tid & 7) << 2;                          \
    float4 pa[2], pw[2];                                                      \
    _Pragma("unroll")                                                         \
    for (int p = 0; p < 2; p++) {                                             \
        int row = lrow + p * 64;                                              \
        pa[p] = *(const float4*)((APTR) + (long)(m0 + row) * E_DIM + lkc);    \
        pw[p] = *(const float4*)((WPTR) + (long)(n0 + row) * E_DIM + lkc);    \
    }                                                                         \
    _Pragma("unroll")                                                         \
    for (int p = 0; p < 2; p++) {                                             \
        int row = lrow + p * 64;                                              \
        As[(lkc + 0) * LDA + row] = f2tf(pa[p].x);                            \
        As[(lkc + 1) * LDA + row] = f2tf(pa[p].y);                            \
        As[(lkc + 2) * LDA + row] = f2tf(pa[p].z);                            \
        As[(lkc + 3) * LDA + row] = f2tf(pa[p].w);                            \
        Bs[(lkc + 0) * LDA + row] = f2tf(pw[p].x);                            \
        Bs[(lkc + 1) * LDA + row] = f2tf(pw[p].y);                            \
        Bs[(lkc + 2) * LDA + row] = f2tf(pw[p].z);                            \
        Bs[(lkc + 3) * LDA + row] = f2tf(pw[p].w);                            \
    }                                                                         \
    for (int it = 0; it < E_DIM / PBK; it++) {                                \
        const int cur = (it & 1) * PBK;                                       \
        __syncthreads();                                                      \
        if (it < E_DIM / PBK - 1) {                                           \
            int k0 = (it + 1) * PBK;                                          \
            _Pragma("unroll")                                                 \
            for (int p = 0; p < 2; p++) {                                     \
                int row = lrow + p * 64;                                      \
                pa[p] = *(const float4*)((APTR) + (long)(m0 + row) * E_DIM + k0 + lkc); \
                pw[p] = *(const float4*)((WPTR) + (long)(n0 + row) * E_DIM + k0 + lkc); \
            }                                                                 \
        }                                                                     \
        _Pragma("unroll")                                                     \
        for (int ks = 0; ks < PBK; ks += 8) {                                 \
            uint32_t af[2][4], bf[4][2];                                      \
            _Pragma("unroll")                                                 \
            for (int mt = 0; mt < 2; mt++) {                                  \
                int r = wm + mt * 16 + g;                                     \
                af[mt][0] = As[(cur + ks + tg) * LDA + r];                    \
                af[mt][1] = As[(cur + ks + tg) * LDA + r + 8];                \
                af[mt][2] = As[(cur + ks + tg + 4) * LDA + r];                \
                af[mt][3] = As[(cur + ks + tg + 4) * LDA + r + 8];            \
            }                                                                 \
            _Pragma("unroll")                                                 \
            for (int nt = 0; nt < 4; nt++) {                                  \
                int n = wn + nt * 8 + g;                                      \
                bf[nt][0] = Bs[(cur + ks + tg) * LDA + n];                    \
                bf[nt][1] = Bs[(cur + ks + tg + 4) * LDA + n];                \
            }                                                                 \
            _Pragma("unroll")                                                 \
            for (int mt = 0; mt < 2; mt++)                                    \
                _Pragma("unroll")                                             \
                for (int nt = 0; nt < 4; nt++)                                \
                    mma8(acc[mt][nt], af[mt], bf[nt]);                        \
        }                                                                     \
        if (it < E_DIM / PBK - 1) {                                           \
            const int nxt = ((it + 1) & 1) * PBK;                             \
            _Pragma("unroll")                                                 \
            for (int p = 0; p < 2; p++) {                                     \
                int row = lrow + p * 64;                                      \
                As[(nxt + lkc + 0) * LDA + row] = f2tf(pa[p].x);              \
                As[(nxt + lkc + 1) * LDA + row] = f2tf(pa[p].y);              \
                As[(nxt + lkc + 2) * LDA + row] = f2tf(pa[p].z);              \
                As[(nxt + lkc + 3) * LDA + row] = f2tf(pa[p].w);              \
                Bs[(nxt + lkc + 0) * LDA + row] = f2tf(pw[p].x);              \
                Bs[(nxt + lkc + 1) * LDA + row] = f2tf(pw[p].y);              \
                Bs[(nxt + lkc + 2) * LDA + row] = f2tf(pw[p].z);              \
                Bs[(nxt + lkc + 3) * LDA + row] = f2tf(pw[p].w);              \
            }                                                                 \
        }                                                                     \
    }

#define GEMM_PROLOGUE                                                         \
    extern __shared__ uint32_t dsm[];                                         \
    uint32_t* As = dsm;                                                       \
    uint32_t* Bs = dsm + 2 * PBK * LDA;                                       \
    const int tid = threadIdx.x, lane = tid & 31, wid = tid >> 5;             \
    const int wm = (wid >> 2) * 32, wn = (wid & 3) * 32;                      \
    const int g = lane >> 2, tg = lane & 3;                                   \
    float acc[2][4][4];                                                       \
    _Pragma("unroll")                                                         \
    for (int i = 0; i < 2; i++)                                               \
        _Pragma("unroll")                                                     \
        for (int j = 0; j < 4; j++)                                           \
            _Pragma("unroll")                                                 \
            for (int q = 0; q < 4; q++) acc[i][j][q] = 0.f;

#define GEMM_EPILOGUE(CPTR, BIASPTR, ALPHA)                                   \
    _Pragma("unroll")                                                         \
    for (int mt = 0; mt < 2; mt++) {                                          \
        int r0 = m0 + wm + mt * 16 + g;                                       \
        _Pragma("unroll")                                                     \
        for (int nt = 0; nt < 4; nt++) {                                      \
            int c = n0 + wn + nt * 8 + 2 * tg;                                \
            float2 bv = *(const float2*)((BIASPTR) + c);                      \
            float2 o0, o1;                                                    \
            o0.x = (ALPHA) * (acc[mt][nt][0] + bv.x);                         \
            o0.y = (ALPHA) * (acc[mt][nt][1] + bv.y);                         \
            o1.x = (ALPHA) * (acc[mt][nt][2] + bv.x);                         \
            o1.y = (ALPHA) * (acc[mt][nt][3] + bv.y);                         \
            *(float2*)((CPTR) + (long)r0 * E_DIM + c) = o0;                   \
            *(float2*)((CPTR) + (long)(r0 + 8) * E_DIM + c) = o1;             \
        }                                                                     \
    }

// ---------------------------------------------------------------------------
// Merged QKV projection: grid (24, 32); seg = blockIdx.x>>3 picks q/k/v.
// ---------------------------------------------------------------------------
__global__ void __launch_bounds__(512) gemm_qkv(
    const float* __restrict__ query, const float* __restrict__ key,
    const float* __restrict__ value, const float* __restrict__ ipw,
    const float* __restrict__ ipb,
    float* __restrict__ Qo, float* __restrict__ Ko, float* __restrict__ Vo)
{
    GEMM_PROLOGUE
    const int m0 = blockIdx.y * 128;
    const int seg = blockIdx.x >> 3;
    const int n0 = (blockIdx.x & 7) * 128;

    const float* A = (seg == 0) ? query : (seg == 1) ? key : value;
    const float* W = ipw + (long)seg * E_DIM * E_DIM;
    const float* bias = ipb + seg * E_DIM;
    float* C = (seg == 0) ? Qo : (seg == 1) ? Ko : Vo;
    const float alpha = (seg == 0) ? 0.125f : 1.0f;

    GEMM_DB_CORE(A, W)
    GEMM_EPILOGUE(C, bias, alpha)
}

// ---------------------------------------------------------------------------
// Output projection
// ---------------------------------------------------------------------------
__global__ void __launch_bounds__(512) gemm_out(
    const float* __restrict__ Ain, const float* __restrict__ W,
    const float* __restrict__ bias, float* __restrict__ C)
{
    GEMM_PROLOGUE
    const int m0 = blockIdx.y * 128, n0 = blockIdx.x * 128;

    GEMM_DB_CORE(Ain, W)
    GEMM_EPILOGUE(C, bias, 1.0f)
}

// ---------------------------------------------------------------------------
// Score kernel: 512 threads, whole K=64 staged once (single sync).
// scores[z][T,S] = Q K^T + attn_mask + pad. 16 warps (4m x 4n), 32x32 tiles.
// SMEM: As[64][132] | Bs[64][132]  = 67584 bytes
// ---------------------------------------------------------------------------
#define SCORE_SMEM_BYTES (2 * 64 * LDA * 4)

__global__ void __launch_bounds__(512) score_kernel(
    const float* __restrict__ Q, const float* __restrict__ Kx,
    const float* __restrict__ amask, const int* __restrict__ pad,
    float* __restrict__ Sc)
{
    extern __shared__ uint32_t dsm[];
    uint32_t* As = dsm;                 // [64][132]
    uint32_t* Bs = dsm + 64 * LDA;      // [64][132]
    const int tid = threadIdx.x, lane = tid & 31, wid = tid >> 5;
    const int wm = (wid >> 2) * 32, wn = (wid & 3) * 32;
    const int t0 = blockIdx.y * 128, s0 = blockIdx.x * 128;
    const int z = blockIdx.z;
    const int b = z >> 4, h = z & 15;
    const int g = lane >> 2, tg = lane & 3;
    const float* Qb = Q + (long)b * E_DIM + h * D_DIM;
    const float* Kb = Kx + (long)b * E_DIM + h * D_DIM;

    float acc[2][4][4];
    #pragma unroll
    for (int i = 0; i < 2; i++)
        #pragma unroll
        for (int j = 0; j < 4; j++)
            #pragma unroll
            for (int q = 0; q < 4; q++) acc[i][j][q] = 0.f;

    // stage all K=64: each thread 4 float4 per array
    {
        const int row = tid >> 2;            // 0..127
        const int d4b = (tid & 3) << 2;      // 0,4,8,12
        #pragma unroll
        for (int p = 0; p < 4; p++) {
            int d4 = d4b + p * 16;
            float4 q4 = *(const float4*)(Qb + (long)(t0 + row) * BE + d4);
            float4 k4 = *(const float4*)(Kb + (long)(s0 + row) * BE + d4);
            As[(d4 + 0) * LDA + row] = f2tf(q4.x);
            As[(d4 + 1) * LDA + row] = f2tf(q4.y);
            As[(d4 + 2) * LDA + row] = f2tf(q4.z);
            As[(d4 + 3) * LDA + row] = f2tf(q4.w);
            Bs[(d4 + 0) * LDA + row] = f2tf(k4.x);
            Bs[(d4 + 1) * LDA + row] = f2tf(k4.y);
            Bs[(d4 + 2) * LDA + row] = f2tf(k4.z);
            Bs[(d4 + 3) * LDA + row] = f2tf(k4.w);
        }
    }
    __syncthreads();

    #pragma unroll
    for (int ks = 0; ks < 64; ks += 8) {
        uint32_t af[2][4], bf[4][2];
        #pragma unroll
        for (int mt = 0; mt < 2; mt++) {
            int r = wm + mt * 16 + g;
            af[mt][0] = As[(ks + tg) * LDA + r];
            af[mt][1] = As[(ks + tg) * LDA + r + 8];
            af[mt][2] = As[(ks + tg + 4) * LDA + r];
            af[mt][3] = As[(ks + tg + 4) * LDA + r + 8];
        }
        #pragma unroll
        for (int nt = 0; nt < 4; nt++) {
            int n = wn + nt * 8 + g;
            bf[nt][0] = Bs[(ks + tg) * LDA + n];
            bf[nt][1] = Bs[(ks + tg + 4) * LDA + n];
        }
        #pragma unroll
        for (int mt = 0; mt < 2; mt++)
            #pragma unroll
            for (int nt = 0; nt < 4; nt++)
                mma8(acc[mt][nt], af[mt], bf[nt]);
    }

    float* So = Sc + (long)z * T_DIM * S_DIM;
    #pragma unroll
    for (int mt = 0; mt < 2; mt++) {
        int t = t0 + wm + mt * 16 + g;
        #pragma unroll
        for (int nt = 0; nt < 4; nt++) {
            int s = s0 + wn + nt * 8 + 2 * tg;
            float p0 = pad[b * S_DIM + s]     ? -1e30f : 0.f;
            float p1 = pad[b * S_DIM + s + 1] ? -1e30f : 0.f;
            float2 a0 = *(const float2*)(amask + (long)t * S_DIM + s);
            float2 a1 = *(const float2*)(amask + (long)(t + 8) * S_DIM + s);
            float2 o0, o1;
            o0.x = acc[mt][nt][0] + a0.x + p0;
            o0.y = acc[mt][nt][1] + a0.y + p1;
            o1.x = acc[mt][nt][2] + a1.x + p0;
            o1.y = acc[mt][nt][3] + a1.y + p1;
            *(float2*)(So + (long)t * S_DIM + s) = o0;
            *(float2*)(So + (long)(t + 8) * S_DIM + s) = o1;
        }
    }
}

// ---------------------------------------------------------------------------
// Softmax + head-average (unchanged from R6): block = (b,t), 16 warps = heads.
// ---------------------------------------------------------------------------
#define SA_SMEM_BYTES (H_DIM * S_DIM * 4)   // 65536

__global__ void __launch_bounds__(512) softmax_avg(
    float* __restrict__ P, float* __restrict__ avgw)
{
    extern __shared__ float Ps[];            // [16][1024]
    const int bid = blockIdx.x;
    const int b = bid >> 10, t = bid & 1023;
    const int h = threadIdx.x >> 5, lane = threadIdx.x & 31;

    float4* p = (float4*)(P + (((long)(b * H_DIM + h) * T_DIM) + t) * S_DIM);
    float4 v[8];
    float m = -1e30f;
    #pragma unroll
    for (int i = 0; i < 8; i++) {
        v[i] = p[lane + 32 * i];
        m = fmaxf(m, fmaxf(fmaxf(v[i].x, v[i].y), fmaxf(v[i].z, v[i].w)));
    }
    #pragma unroll
    for (int o = 16; o; o >>= 1) m = fmaxf(m, __shfl_xor_sync(0xffffffffu, m, o));
    float sum = 0.f;
    #pragma unroll
    for (int i = 0; i < 8; i++) {
        v[i].x = __expf(v[i].x - m); v[i].y = __expf(v[i].y - m);
        v[i].z = __expf(v[i].z - m); v[i].w = __expf(v[i].w - m);
        sum += v[i].x + v[i].y + v[i].z + v[i].w;
    }
    #pragma unroll
    for (int o = 16; o; o >>= 1) sum += __shfl_xor_sync(0xffffffffu, sum, o);
    float inv = 1.0f / sum;
    float4* ps = (float4*)(Ps + h * S_DIM);
    #pragma unroll
    for (int i = 0; i < 8; i++) {
        v[i].x *= inv; v[i].y *= inv; v[i].z *= inv; v[i].w *= inv;
        p[lane + 32 * i] = v[i];
        ps[lane + 32 * i] = v[i];
    }
    __syncthreads();

    int s2 = threadIdx.x * 2;
    float a0 = 0.f, a1 = 0.f;
    #pragma unroll
    for (int hh = 0; hh < H_DIM; hh++) {
        float2 pv = *(const float2*)(Ps + hh * S_DIM + s2);
        a0 += pv.x; a1 += pv.y;
    }
    const float inv16 = 1.0f / H_DIM;
    *(float2*)(avgw + ((long)b * T_DIM + t) * S_DIM + s2) =
        make_float2(a0 * inv16, a1 * inv16);
}

// ---------------------------------------------------------------------------
// PV: Ctx[b,h] (T x 64) = P[z] @ V[b,h]. 512 threads, 16 warps (8m x 2n),
// warp tile 16x32 (acc 16 regs). Double-buffered.
// SMEM: As[2*PBK][LDA] | Bs[2*PBK][VLDB]
// ---------------------------------------------------------------------------
#define VLDB 72
#define PV_SMEM_BYTES ((2 * PBK * LDA + 2 * PBK * VLDB) * 4)   // 52224

__global__ void __launch_bounds__(512) pv_kernel(
    const float* __restrict__ Sc, const float* __restrict__ V,
    float* __restrict__ Ctx)
{
    extern __shared__ uint32_t dsm[];
    uint32_t* As = dsm;                       // [2*PBK][LDA]
    uint32_t* Bs = dsm + 2 * PBK * LDA;       // [2*PBK][VLDB]
    const int tid = threadIdx.x, lane = tid & 31, wid = tid >> 5;
    const int wm = (wid >> 1) * 16, wn = (wid & 1) * 32;
    const int t0 = blockIdx.x * 128;
    const int z = blockIdx.z;
    const int b = z >> 4, h = z & 15;
    const int g = lane >> 2, tg = lane & 3;
    const float* Pb = Sc + (long)z * T_DIM * S_DIM;
    const float* Vb = V + (long)b * E_DIM + h * D_DIM;

    float acc[4][4];
    #pragma unroll
    for (int j = 0; j < 4; j++)
        #pragma unroll
        for (int q = 0; q < 4; q++) acc[j][q] = 0.f;

    const int arow = tid >> 3, akc = (tid & 7) << 2;   // rows arow + p*64
    const int bs_s = tid >> 4, bs_d = (tid & 15) << 2; // 32 s-rows, 64 d

    float4 pa[2], pv;
    #pragma unroll
    for (int p = 0; p < 2; p++)
        pa[p] = *(const float4*)(Pb + (long)(t0 + arow + p * 64) * S_DIM + akc);
    pv = *(const float4*)(Vb + (long)bs_s * BE + bs_d);

    #pragma unroll
    for (int p = 0; p < 2; p++) {
        int row = arow + p * 64;
        As[(akc + 0) * LDA + row] = f2tf(pa[p].x);
        As[(akc + 1) * LDA + row] = f2tf(pa[p].y);
        As[(akc + 2) * LDA + row] = f2tf(pa[p].z);
        As[(akc + 3) * LDA + row] = f2tf(pa[p].w);
    }
    Bs[bs_s * VLDB + bs_d + 0] = f2tf(pv.x);
    Bs[bs_s * VLDB + bs_d + 1] = f2tf(pv.y);
    Bs[bs_s * VLDB + bs_d + 2] = f2tf(pv.z);
    Bs[bs_s * VLDB + bs_d + 3] = f2tf(pv.w);

    for (int it = 0; it < S_DIM / PBK; it++) {
        const int cur = (it & 1) * PBK;
        __syncthreads();
        if (it < S_DIM / PBK - 1) {
            int k0 = (it + 1) * PBK;
            #pragma unroll
            for (int p = 0; p < 2; p++)
                pa[p] = *(const float4*)(Pb + (long)(t0 + arow + p * 64) * S_DIM + k0 + akc);
            pv = *(const float4*)(Vb + (long)(k0 + bs_s) * BE + bs_d);
        }
        #pragma unroll
        for (int ks = 0; ks < PBK; ks += 8) {
            uint32_t af[4], bf[4][2];
            int r = wm + g;
            af[0] = As[(cur + ks + tg) * LDA + r];
            af[1] = As[(cur + ks + tg) * LDA + r + 8];
            af[2] = As[(cur + ks + tg + 4) * LDA + r];
            af[3] = As[(cur + ks + tg + 4) * LDA + r + 8];
            #pragma unroll
            for (int nt = 0; nt < 4; nt++) {
                int n = wn + nt * 8 + g;
                bf[nt][0] = Bs[(cur + ks + tg) * VLDB + n];
                bf[nt][1] = Bs[(cur + ks + tg + 4) * VLDB + n];
            }
            #pragma unroll
            for (int nt = 0; nt < 4; nt++)
                mma8(acc[nt], af, bf[nt]);
        }
        if (it < S_DIM / PBK - 1) {
            const int nxt = ((it + 1) & 1) * PBK;
            #pragma unroll
            for (int p = 0; p < 2; p++) {
                int row = arow + p * 64;
                As[(nxt + akc + 0) * LDA + row] = f2tf(pa[p].x);
                As[(nxt + akc + 1) * LDA + row] = f2tf(pa[p].y);
                As[(nxt + akc + 2) * LDA + row] = f2tf(pa[p].z);
                As[(nxt + akc + 3) * LDA + row] = f2tf(pa[p].w);
            }
            Bs[(nxt + bs_s) * VLDB + bs_d + 0] = f2tf(pv.x);
            Bs[(nxt + bs_s) * VLDB + bs_d + 1] = f2tf(pv.y);
            Bs[(nxt + bs_s) * VLDB + bs_d + 2] = f2tf(pv.z);
            Bs[(nxt + bs_s) * VLDB + bs_d + 3] = f2tf(pv.w);
        }
    }

    {
        int t = t0 + wm + g;
        #pragma unroll
        for (int nt = 0; nt < 4; nt++) {
            int d = wn + nt * 8 + 2 * tg;
            *(float2*)(Ctx + (long)t * BE + b * E_DIM + h * D_DIM + d) =
                make_float2(acc[nt][0], acc[nt][1]);
            *(float2*)(Ctx + (long)(t + 8) * BE + b * E_DIM + h * D_DIM + d) =
                make_float2(acc[nt][2], acc[nt][3]);
        }
    }
}

// ---------------------------------------------------------------------------
extern "C" void kernel_launch(void* const* d_in, const int* in_sizes, int n_in,
                              void* d_out, int out_size) {
    const float* query = (const float*)d_in[0];
    const float* key   = (const float*)d_in[1];
    const float* value = (const float*)d_in[2];
    const int*   pad   = (const int*)d_in[3];
    const float* amask = (const float*)d_in[4];
    const float* ipw   = (const float*)d_in[5];
    const float* ipb   = (const float*)d_in[6];
    const float* ow    = (const float*)d_in[7];
    const float* ob    = (const float*)d_in[8];

    float* out  = (float*)d_out;
    float* avgw = out + (long)T_DIM * B_DIM * E_DIM;

    float *Qp, *Kp, *Vp, *Cp, *Pp;
    cudaGetSymbolAddress((void**)&Qp, g_Q);
    cudaGetSymbolAddress((void**)&Kp, g_K);
    cudaGetSymbolAddress((void**)&Vp, g_V);
    cudaGetSymbolAddress((void**)&Cp, g_Ctx);
    cudaGetSymbolAddress((void**)&Pp, g_P);

    cudaFuncSetAttribute(gemm_qkv,
        cudaFuncAttributeMaxDynamicSharedMemorySize, GEMM_SMEM_BYTES);
    cudaFuncSetAttribute(gemm_out,
        cudaFuncAttributeMaxDynamicSharedMemorySize, GEMM_SMEM_BYTES);
    cudaFuncSetAttribute(score_kernel,
        cudaFuncAttributeMaxDynamicSharedMemorySize, SCORE_SMEM_BYTES);
    cudaFuncSetAttribute(softmax_avg,
        cudaFuncAttributeMaxDynamicSharedMemorySize, SA_SMEM_BYTES);
    cudaFuncSetAttribute(pv_kernel,
        cudaFuncAttributeMaxDynamicSharedMemorySize, PV_SMEM_BYTES);

    gemm_qkv<<<dim3(24, 32), 512, GEMM_SMEM_BYTES>>>(
        query, key, value, ipw, ipb, Qp, Kp, Vp);

    score_kernel<<<dim3(8, 8, 64), 512, SCORE_SMEM_BYTES>>>(
        Qp, Kp, amask, pad, Pp);

    softmax_avg<<<B_DIM * T_DIM, 512, SA_SMEM_BYTES>>>(Pp, avgw);

    pv_kernel<<<dim3(8, 1, 64), 512, PV_SMEM_BYTES>>>(Pp, Vp, Cp);

    gemm_out<<<dim3(8, 32), 512, GEMM_SMEM_BYTES>>>(Cp, ow, ob, out);
}

// round 9
// speedup vs baseline: 1.1480x; 1.1480x over previous
#include <cuda_runtime.h>
#include <cstdint>

// Problem constants
#define T_DIM 1024
#define B_DIM 4
#define S_DIM 1024
#define E_DIM 1024
#define H_DIM 16
#define D_DIM 64
#define TB (T_DIM * B_DIM)
#define BE (B_DIM * E_DIM)

// Scratch (device globals — no allocation allowed)
__device__ float g_Q[TB * E_DIM];
__device__ float g_K[TB * E_DIM];
__device__ float g_V[TB * E_DIM];
__device__ float g_Ctx[TB * E_DIM];
__device__ float g_P[(long)B_DIM * H_DIM * T_DIM * S_DIM];   // scores -> probs (256 MB)

// ---------------------------------------------------------------------------
// tf32 helpers
// ---------------------------------------------------------------------------
__device__ __forceinline__ uint32_t f2tf(float x) {
    uint32_t r;
    asm("cvt.rna.tf32.f32 %0, %1;" : "=r"(r) : "f"(x));
    return r;
}

__device__ __forceinline__ void mma8(float* d, const uint32_t* a, const uint32_t* b) {
    asm volatile(
        "mma.sync.aligned.m16n8k8.row.col.f32.tf32.tf32.f32 "
        "{%0,%1,%2,%3}, {%4,%5,%6,%7}, {%8,%9}, {%0,%1,%2,%3};\n"
        : "+f"(d[0]), "+f"(d[1]), "+f"(d[2]), "+f"(d[3])
        : "r"(a[0]), "r"(a[1]), "r"(a[2]), "r"(a[3]), "r"(b[0]), "r"(b[1]));
}

#define PBK 32
#define LDA 132

// ---------------------------------------------------------------------------
// Fragment-interleaved GEMM (128x128x32, 256 thr, 8 warps 2m x 4n, tile 64x32)
// A region (per stage, 4096 words): block (sb=k/8, mb=m/16); word =
//   ((sb*8+mb)*32 + (m%8)*4 + (k%4))*4 + ((k%8)>=4)*2 + ((m%16)>=8)
// B region (per stage, 4096 words): block (sb, nb8=n/8); word =
//   ((sb*16+nb8)*32 + (n%8)*4 + (k%4))*2 + ((k%8)>=4)
// Mainloop: a-frag = 1 LDS.128, b-frag = 1 LDS.64.
// ---------------------------------------------------------------------------
#define GEMM_SMEM_WORDS 16384
#define GEMM_SMEM_BYTES (GEMM_SMEM_WORDS * 4)   // 65536

#define GEMM_STAGE(DSTA, DSTB, PA, PW)                                        \
    _Pragma("unroll")                                                         \
    for (int p = 0; p < 4; p++) {                                             \
        int row = lrow + p * 32;                                              \
        int mbq = row >> 4, fragm = ((row & 15) >= 8) ? 1 : 0;                \
        int nb8 = row >> 3;                                                   \
        int laneb = (row & 7) * 4;                                            \
        uint32_t* aw = (DSTA) + ((sbq * 8 + mbq) * 32 + laneb) * 4 + fragk2 + fragm; \
        uint32_t* bw = (DSTB) + ((sbq * 16 + nb8) * 32 + laneb) * 2 + fragb;  \
        aw[0]  = f2tf((PA)[p].x); aw[4]  = f2tf((PA)[p].y);                   \
        aw[8]  = f2tf((PA)[p].z); aw[12] = f2tf((PA)[p].w);                   \
        bw[0]  = f2tf((PW)[p].x); bw[2]  = f2tf((PW)[p].y);                   \
        bw[4]  = f2tf((PW)[p].z); bw[6]  = f2tf((PW)[p].w);                   \
    }

#define GEMM_DB_CORE(APTR, WPTR)                                              \
    const int lrow = tid >> 3, lkc = (tid & 7) << 2;                          \
    const int sbq = lkc >> 3;                                                 \
    const int fragk2 = ((lkc & 7) >= 4) ? 2 : 0;                              \
    const int fragb  = ((lkc & 7) >= 4) ? 1 : 0;                              \
    float4 pa[4], pw[4];                                                      \
    _Pragma("unroll")                                                         \
    for (int p = 0; p < 4; p++) {                                             \
        int row = lrow + p * 32;                                              \
        pa[p] = *(const float4*)((APTR) + (long)(m0 + row) * E_DIM + lkc);    \
        pw[p] = *(const float4*)((WPTR) + (long)(n0 + row) * E_DIM + lkc);    \
    }                                                                         \
    GEMM_STAGE(As, Bs, pa, pw)                                                \
    for (int it = 0; it < E_DIM / PBK; it++) {                                \
        const int cur = (it & 1) * 4096;                                      \
        __syncthreads();                                                      \
        if (it < E_DIM / PBK - 1) {                                           \
            int k0 = (it + 1) * PBK;                                          \
            _Pragma("unroll")                                                 \
            for (int p = 0; p < 4; p++) {                                     \
                int row = lrow + p * 32;                                      \
                pa[p] = *(const float4*)((APTR) + (long)(m0 + row) * E_DIM + k0 + lkc); \
                pw[p] = *(const float4*)((WPTR) + (long)(n0 + row) * E_DIM + k0 + lkc); \
            }                                                                 \
        }                                                                     \
        const uint32_t* Acur = As + cur;                                      \
        const uint32_t* Bcur = Bs + cur;                                      \
        _Pragma("unroll")                                                     \
        for (int sb = 0; sb < 4; sb++) {                                      \
            uint4 af[4];                                                      \
            uint2 bf[4];                                                      \
            _Pragma("unroll")                                                 \
            for (int mt = 0; mt < 4; mt++)                                    \
                af[mt] = *(const uint4*)(Acur + ((sb * 8 + wmb + mt) * 32 + lane) * 4); \
            _Pragma("unroll")                                                 \
            for (int nt = 0; nt < 4; nt++)                                    \
                bf[nt] = *(const uint2*)(Bcur + ((sb * 16 + wnb + nt) * 32 + lane) * 2); \
            _Pragma("unroll")                                                 \
            for (int mt = 0; mt < 4; mt++)                                    \
                _Pragma("unroll")                                             \
                for (int nt = 0; nt < 4; nt++)                                \
                    mma8(acc[mt][nt], (const uint32_t*)&af[mt], (const uint32_t*)&bf[nt]); \
        }                                                                     \
        if (it < E_DIM / PBK - 1) {                                           \
            const int nxt = ((it + 1) & 1) * 4096;                            \
            GEMM_STAGE(As + nxt, Bs + nxt, pa, pw)                            \
        }                                                                     \
    }

#define GEMM_PROLOGUE                                                         \
    extern __shared__ uint32_t dsm[];                                         \
    uint32_t* As = dsm;                                                       \
    uint32_t* Bs = dsm + 8192;                                                \
    const int tid = threadIdx.x, lane = tid & 31, wid = tid >> 5;             \
    const int wm = (wid >> 2) * 64, wn = (wid & 3) * 32;                      \
    const int wmb = wm >> 4, wnb = wn >> 3;                                   \
    const int g = lane >> 2, tg = lane & 3;                                   \
    float acc[4][4][4];                                                       \
    _Pragma("unroll")                                                         \
    for (int i = 0; i < 4; i++)                                               \
        _Pragma("unroll")                                                     \
        for (int j = 0; j < 4; j++)                                           \
            _Pragma("unroll")                                                 \
            for (int q = 0; q < 4; q++) acc[i][j][q] = 0.f;

#define GEMM_EPILOGUE(CPTR, BIASPTR, ALPHA)                                   \
    _Pragma("unroll")                                                         \
    for (int mt = 0; mt < 4; mt++) {                                          \
        int r0 = m0 + wm + mt * 16 + g;                                       \
        _Pragma("unroll")                                                     \
        for (int nt = 0; nt < 4; nt++) {                                      \
            int c = n0 + wn + nt * 8 + 2 * tg;                                \
            float2 bv = *(const float2*)((BIASPTR) + c);                      \
            float2 o0, o1;                                                    \
            o0.x = (ALPHA) * (acc[mt][nt][0] + bv.x);                         \
            o0.y = (ALPHA) * (acc[mt][nt][1] + bv.y);                         \
            o1.x = (ALPHA) * (acc[mt][nt][2] + bv.x);                         \
            o1.y = (ALPHA) * (acc[mt][nt][3] + bv.y);                         \
            *(float2*)((CPTR) + (long)r0 * E_DIM + c) = o0;                   \
            *(float2*)((CPTR) + (long)(r0 + 8) * E_DIM + c) = o1;             \
        }                                                                     \
    }

// ---------------------------------------------------------------------------
// Merged QKV projection: grid (24, 32); seg = blockIdx.x>>3 picks q/k/v.
// ---------------------------------------------------------------------------
__global__ void __launch_bounds__(256) gemm_qkv(
    const float* __restrict__ query, const float* __restrict__ key,
    const float* __restrict__ value, const float* __restrict__ ipw,
    const float* __restrict__ ipb,
    float* __restrict__ Qo, float* __restrict__ Ko, float* __restrict__ Vo)
{
    GEMM_PROLOGUE
    const int m0 = blockIdx.y * 128;
    const int seg = blockIdx.x >> 3;
    const int n0 = (blockIdx.x & 7) * 128;

    const float* A = (seg == 0) ? query : (seg == 1) ? key : value;
    const float* W = ipw + (long)seg * E_DIM * E_DIM;
    const float* bias = ipb + seg * E_DIM;
    float* C = (seg == 0) ? Qo : (seg == 1) ? Ko : Vo;
    const float alpha = (seg == 0) ? 0.125f : 1.0f;

    GEMM_DB_CORE(A, W)
    GEMM_EPILOGUE(C, bias, alpha)
}

// ---------------------------------------------------------------------------
// Output projection
// ---------------------------------------------------------------------------
__global__ void __launch_bounds__(256) gemm_out(
    const float* __restrict__ Ain, const float* __restrict__ W,
    const float* __restrict__ bias, float* __restrict__ C)
{
    GEMM_PROLOGUE
    const int m0 = blockIdx.y * 128, n0 = blockIdx.x * 128;

    GEMM_DB_CORE(Ain, W)
    GEMM_EPILOGUE(C, bias, 1.0f)
}

// ---------------------------------------------------------------------------
// Score kernel (R6 verbatim): scores[z][T,S] = Q K^T + attn_mask + pad
// ---------------------------------------------------------------------------
__global__ void __launch_bounds__(256) score_kernel(
    const float* __restrict__ Q, const float* __restrict__ Kx,
    const float* __restrict__ amask, const int* __restrict__ pad,
    float* __restrict__ Sc)
{
    __shared__ uint32_t As[PBK][LDA];
    __shared__ uint32_t Bs[PBK][LDA];
    const int tid = threadIdx.x, lane = tid & 31, wid = tid >> 5;
    const int wm = (wid >> 2) * 64, wn = (wid & 3) * 32;
    const int t0 = blockIdx.y * 128, s0 = blockIdx.x * 128;
    const int z = blockIdx.z;
    const int b = z >> 4, h = z & 15;
    const int g = lane >> 2, tg = lane & 3;
    const float* Qb = Q + (long)b * E_DIM + h * D_DIM;
    const float* Kb = Kx + (long)b * E_DIM + h * D_DIM;

    float acc[4][4][4];
    #pragma unroll
    for (int i = 0; i < 4; i++)
        #pragma unroll
        for (int j = 0; j < 4; j++)
            #pragma unroll
            for (int q = 0; q < 4; q++) acc[i][j][q] = 0.f;

    #pragma unroll
    for (int k0 = 0; k0 < D_DIM; k0 += PBK) {
        #pragma unroll
        for (int p = 0; p < 4; p++) {
            int idx = tid + p * 256;
            int row = idx >> 3, kc = (idx & 7) << 2;
            float4 q4 = *(const float4*)(Qb + (long)(t0 + row) * BE + k0 + kc);
            float4 k4 = *(const float4*)(Kb + (long)(s0 + row) * BE + k0 + kc);
            As[kc + 0][row] = f2tf(q4.x); As[kc + 1][row] = f2tf(q4.y);
            As[kc + 2][row] = f2tf(q4.z); As[kc + 3][row] = f2tf(q4.w);
            Bs[kc + 0][row] = f2tf(k4.x); Bs[kc + 1][row] = f2tf(k4.y);
            Bs[kc + 2][row] = f2tf(k4.z); Bs[kc + 3][row] = f2tf(k4.w);
        }
        __syncthreads();
        #pragma unroll
        for (int ks = 0; ks < PBK; ks += 8) {
            uint32_t af[4][4], bf[4][2];
            #pragma unroll
            for (int mt = 0; mt < 4; mt++) {
                int r = wm + mt * 16 + g;
                af[mt][0] = As[ks + tg][r];
                af[mt][1] = As[ks + tg][r + 8];
                af[mt][2] = As[ks + tg + 4][r];
                af[mt][3] = As[ks + tg + 4][r + 8];
            }
            #pragma unroll
            for (int nt = 0; nt < 4; nt++) {
                int n = wn + nt * 8 + g;
                bf[nt][0] = Bs[ks + tg][n];
                bf[nt][1] = Bs[ks + tg + 4][n];
            }
            #pragma unroll
            for (int mt = 0; mt < 4; mt++)
                #pragma unroll
                for (int nt = 0; nt < 4; nt++)
                    mma8(acc[mt][nt], af[mt], bf[nt]);
        }
        __syncthreads();
    }

    float* So = Sc + (long)z * T_DIM * S_DIM;
    #pragma unroll
    for (int mt = 0; mt < 4; mt++) {
        int t = t0 + wm + mt * 16 + g;
        #pragma unroll
        for (int nt = 0; nt < 4; nt++) {
            int s = s0 + wn + nt * 8 + 2 * tg;
            float p0 = pad[b * S_DIM + s]     ? -1e30f : 0.f;
            float p1 = pad[b * S_DIM + s + 1] ? -1e30f : 0.f;
            float2 a0 = *(const float2*)(amask + (long)t * S_DIM + s);
            float2 a1 = *(const float2*)(amask + (long)(t + 8) * S_DIM + s);
            float2 o0, o1;
            o0.x = acc[mt][nt][0] + a0.x + p0;
            o0.y = acc[mt][nt][1] + a0.y + p1;
            o1.x = acc[mt][nt][2] + a1.x + p0;
            o1.y = acc[mt][nt][3] + a1.y + p1;
            *(float2*)(So + (long)t * S_DIM + s) = o0;
            *(float2*)(So + (long)(t + 8) * S_DIM + s) = o1;
        }
    }
}

// ---------------------------------------------------------------------------
// Softmax + head-average (R6 verbatim): block = (b,t), 16 warps = 16 heads.
// ---------------------------------------------------------------------------
#define SA_SMEM_BYTES (H_DIM * S_DIM * 4)   // 65536

__global__ void __launch_bounds__(512) softmax_avg(
    float* __restrict__ P, float* __restrict__ avgw)
{
    extern __shared__ float Ps[];            // [16][1024]
    const int bid = blockIdx.x;
    const int b = bid >> 10, t = bid & 1023;
    const int h = threadIdx.x >> 5, lane = threadIdx.x & 31;

    float4* p = (float4*)(P + (((long)(b * H_DIM + h) * T_DIM) + t) * S_DIM);
    float4 v[8];
    float m = -1e30f;
    #pragma unroll
    for (int i = 0; i < 8; i++) {
        v[i] = p[lane + 32 * i];
        m = fmaxf(m, fmaxf(fmaxf(v[i].x, v[i].y), fmaxf(v[i].z, v[i].w)));
    }
    #pragma unroll
    for (int o = 16; o; o >>= 1) m = fmaxf(m, __shfl_xor_sync(0xffffffffu, m, o));
    float sum = 0.f;
    #pragma unroll
    for (int i = 0; i < 8; i++) {
        v[i].x = __expf(v[i].x - m); v[i].y = __expf(v[i].y - m);
        v[i].z = __expf(v[i].z - m); v[i].w = __expf(v[i].w - m);
        sum += v[i].x + v[i].y + v[i].z + v[i].w;
    }
    #pragma unroll
    for (int o = 16; o; o >>= 1) sum += __shfl_xor_sync(0xffffffffu, sum, o);
    float inv = 1.0f / sum;
    float4* ps = (float4*)(Ps + h * S_DIM);
    #pragma unroll
    for (int i = 0; i < 8; i++) {
        v[i].x *= inv; v[i].y *= inv; v[i].z *= inv; v[i].w *= inv;
        p[lane + 32 * i] = v[i];
        ps[lane + 32 * i] = v[i];
    }
    __syncthreads();

    int s2 = threadIdx.x * 2;
    float a0 = 0.f, a1 = 0.f;
    #pragma unroll
    for (int hh = 0; hh < H_DIM; hh++) {
        float2 pv = *(const float2*)(Ps + hh * S_DIM + s2);
        a0 += pv.x; a1 += pv.y;
    }
    const float inv16 = 1.0f / H_DIM;
    *(float2*)(avgw + ((long)b * T_DIM + t) * S_DIM + s2) =
        make_float2(a0 * inv16, a1 * inv16);
}

// ---------------------------------------------------------------------------
// PV (R6 verbatim): Ctx[b,h] (T x 64) = P[z] @ V[b,h] — double-buffered
// ---------------------------------------------------------------------------
#define VLDB 72
#define PV_SMEM_BYTES ((2 * PBK * LDA + 2 * PBK * VLDB) * 4)   // 52224

__global__ void __launch_bounds__(256) pv_kernel(
    const float* __restrict__ Sc, const float* __restrict__ V,
    float* __restrict__ Ctx)
{
    extern __shared__ uint32_t dsm[];
    uint32_t* As = dsm;                       // [2*PBK][LDA]
    uint32_t* Bs = dsm + 2 * PBK * LDA;       // [2*PBK][VLDB]
    const int tid = threadIdx.x, lane = tid & 31, wid = tid >> 5;
    const int wm = (wid >> 1) * 32, wn = (wid & 1) * 32;
    const int t0 = blockIdx.x * 128;
    const int z = blockIdx.z;
    const int b = z >> 4, h = z & 15;
    const int g = lane >> 2, tg = lane & 3;
    const float* Pb = Sc + (long)z * T_DIM * S_DIM;
    const float* Vb = V + (long)b * E_DIM + h * D_DIM;

    float acc[2][4][4];
    #pragma unroll
    for (int i = 0; i < 2; i++)
        #pragma unroll
        for (int j = 0; j < 4; j++)
            #pragma unroll
            for (int q = 0; q < 4; q++) acc[i][j][q] = 0.f;

    const int arow = tid >> 3, akc = (tid & 7) << 2;
    const int bs_s = tid >> 4, bs_d = (tid & 15) << 2;

    float4 pa[4], pv[2];
    #pragma unroll
    for (int p = 0; p < 4; p++)
        pa[p] = *(const float4*)(Pb + (long)(t0 + arow + p * 32) * S_DIM + akc);
    #pragma unroll
    for (int p = 0; p < 2; p++)
        pv[p] = *(const float4*)(Vb + (long)(bs_s + p * 16) * BE + bs_d);
    #pragma unroll
    for (int p = 0; p < 4; p++) {
        int row = arow + p * 32;
        As[(akc + 0) * LDA + row] = f2tf(pa[p].x);
        As[(akc + 1) * LDA + row] = f2tf(pa[p].y);
        As[(akc + 2) * LDA + row] = f2tf(pa[p].z);
        As[(akc + 3) * LDA + row] = f2tf(pa[p].w);
    }
    #pragma unroll
    for (int p = 0; p < 2; p++) {
        int s = bs_s + p * 16;
        Bs[s * VLDB + bs_d + 0] = f2tf(pv[p].x);
        Bs[s * VLDB + bs_d + 1] = f2tf(pv[p].y);
        Bs[s * VLDB + bs_d + 2] = f2tf(pv[p].z);
        Bs[s * VLDB + bs_d + 3] = f2tf(pv[p].w);
    }

    for (int it = 0; it < S_DIM / PBK; it++) {
        const int cur = (it & 1) * PBK;
        __syncthreads();
        if (it < S_DIM / PBK - 1) {
            int k0 = (it + 1) * PBK;
            #pragma unroll
            for (int p = 0; p < 4; p++)
                pa[p] = *(const float4*)(Pb + (long)(t0 + arow + p * 32) * S_DIM + k0 + akc);
            #pragma unroll
            for (int p = 0; p < 2; p++)
                pv[p] = *(const float4*)(Vb + (long)(k0 + bs_s + p * 16) * BE + bs_d);
        }
        #pragma unroll
        for (int ks = 0; ks < PBK; ks += 8) {
            uint32_t af[2][4], bf[4][2];
            #pragma unroll
            for (int mt = 0; mt < 2; mt++) {
                int r = wm + mt * 16 + g;
                af[mt][0] = As[(cur + ks + tg) * LDA + r];
                af[mt][1] = As[(cur + ks + tg) * LDA + r + 8];
                af[mt][2] = As[(cur + ks + tg + 4) * LDA + r];
                af[mt][3] = As[(cur + ks + tg + 4) * LDA + r + 8];
            }
            #pragma unroll
            for (int nt = 0; nt < 4; nt++) {
                int n = wn + nt * 8 + g;
                bf[nt][0] = Bs[(cur + ks + tg) * VLDB + n];
                bf[nt][1] = Bs[(cur + ks + tg + 4) * VLDB + n];
            }
            #pragma unroll
            for (int mt = 0; mt < 2; mt++)
                #pragma unroll
                for (int nt = 0; nt < 4; nt++)
                    mma8(acc[mt][nt], af[mt], bf[nt]);
        }
        if (it < S_DIM / PBK - 1) {
            const int nxt = ((it + 1) & 1) * PBK;
            #pragma unroll
            for (int p = 0; p < 4; p++) {
                int row = arow + p * 32;
                As[(nxt + akc + 0) * LDA + row] = f2tf(pa[p].x);
                As[(nxt + akc + 1) * LDA + row] = f2tf(pa[p].y);
                As[(nxt + akc + 2) * LDA + row] = f2tf(pa[p].z);
                As[(nxt + akc + 3) * LDA + row] = f2tf(pa[p].w);
            }
            #pragma unroll
            for (int p = 0; p < 2; p++) {
                int s = bs_s + p * 16;
                Bs[(nxt + s) * VLDB + bs_d + 0] = f2tf(pv[p].x);
                Bs[(nxt + s) * VLDB + bs_d + 1] = f2tf(pv[p].y);
                Bs[(nxt + s) * VLDB + bs_d + 2] = f2tf(pv[p].z);
                Bs[(nxt + s) * VLDB + bs_d + 3] = f2tf(pv[p].w);
            }
        }
    }

    #pragma unroll
    for (int mt = 0; mt < 2; mt++) {
        int t = t0 + wm + mt * 16 + g;
        #pragma unroll
        for (int nt = 0; nt < 4; nt++) {
            int d = wn + nt * 8 + 2 * tg;
            *(float2*)(Ctx + (long)t * BE + b * E_DIM + h * D_DIM + d) =
                make_float2(acc[mt][nt][0], acc[mt][nt][1]);
            *(float2*)(Ctx + (long)(t + 8) * BE + b * E_DIM + h * D_DIM + d) =
                make_float2(acc[mt][nt][2], acc[mt][nt][3]);
        }
    }
}

// ---------------------------------------------------------------------------
extern "C" void kernel_launch(void* const* d_in, const int* in_sizes, int n_in,
                              void* d_out, int out_size) {
    const float* query = (const float*)d_in[0];
    const float* key   = (const float*)d_in[1];
    const float* value = (const float*)d_in[2];
    const int*   pad   = (const int*)d_in[3];
    const float* amask = (const float*)d_in[4];
    const float* ipw   = (const float*)d_in[5];
    const float* ipb   = (const float*)d_in[6];
    const float* ow    = (const float*)d_in[7];
    const float* ob    = (const float*)d_in[8];

    float* out  = (float*)d_out;
    float* avgw = out + (long)T_DIM * B_DIM * E_DIM;

    float *Qp, *Kp, *Vp, *Cp, *Pp;
    cudaGetSymbolAddress((void**)&Qp, g_Q);
    cudaGetSymbolAddress((void**)&Kp, g_K);
    cudaGetSymbolAddress((void**)&Vp, g_V);
    cudaGetSymbolAddress((void**)&Cp, g_Ctx);
    cudaGetSymbolAddress((void**)&Pp, g_P);

    cudaFuncSetAttribute(gemm_qkv,
        cudaFuncAttributeMaxDynamicSharedMemorySize, GEMM_SMEM_BYTES);
    cudaFuncSetAttribute(gemm_out,
        cudaFuncAttributeMaxDynamicSharedMemorySize, GEMM_SMEM_BYTES);
    cudaFuncSetAttribute(softmax_avg,
        cudaFuncAttributeMaxDynamicSharedMemorySize, SA_SMEM_BYTES);
    cudaFuncSetAttribute(pv_kernel,
        cudaFuncAttributeMaxDynamicSharedMemorySize, PV_SMEM_BYTES);

    gemm_qkv<<<dim3(24, 32), 256, GEMM_SMEM_BYTES>>>(
        query, key, value, ipw, ipb, Qp, Kp, Vp);

    score_kernel<<<dim3(8, 8, 64), 256>>>(Qp, Kp, amask, pad, Pp);

    softmax_avg<<<B_DIM * T_DIM, 512, SA_SMEM_BYTES>>>(Pp, avgw);

    pv_kernel<<<dim3(8, 1, 64), 256, PV_SMEM_BYTES>>>(Pp, Vp, Cp);

    gemm_out<<<dim3(8, 32), 256, GEMM_SMEM_BYTES>>>(Cp, ow, ob, out);
}